// round 4
// baseline (speedup 1.0000x reference)
#include <cuda_runtime.h>
#include <cstdint>
#include <math.h>

// ---------------- problem constants ----------------
#define BATCH   4
#define SEQ     1024
#define MTOK    (BATCH*SEQ)      // 4096
#define DMODEL  512
#define NHEADS  8
#define DHEAD   64
#define FFDIM   2048
#define NLAYER  6
#define LN_EPS  1e-5f

// ---------------- scratch (no allocation allowed) ----------------
__device__ float g_x   [MTOK*DMODEL];
__device__ float g_q   [MTOK*DMODEL];
__device__ float g_k   [MTOK*DMODEL];
__device__ float g_v   [MTOK*DMODEL];
__device__ float g_attn[MTOK*DMODEL];
__device__ float g_tmp [MTOK*DMODEL];
__device__ float g_h1  [MTOK*FFDIM];

// ---------------- packed f32x2 helpers (Blackwell FFMA2) ----------------
__device__ __forceinline__ unsigned long long pack2(float x, float y) {
    unsigned long long r;
    asm("mov.b64 %0, {%1, %2};" : "=l"(r) : "f"(x), "f"(y));
    return r;
}
__device__ __forceinline__ float2 unpack2(unsigned long long v) {
    float2 r;
    asm("mov.b64 {%0, %1}, %2;" : "=f"(r.x), "=f"(r.y) : "l"(v));
    return r;
}
__device__ __forceinline__ void ffma2(unsigned long long& d,
                                      unsigned long long a,
                                      unsigned long long b) {
    asm("fma.rn.f32x2 %0, %1, %2, %0;" : "+l"(d) : "l"(a), "l"(b));
}

// ---------------- embedding + sinusoidal positional encoding ----------------
__global__ __launch_bounds__(256)
void embed_kernel(const int* __restrict__ tokens,
                  const float* __restrict__ emb,
                  float* __restrict__ x)
{
    int idx = blockIdx.x * blockDim.x + threadIdx.x;   // over MTOK*DMODEL
    if (idx >= MTOK*DMODEL) return;
    int m = idx >> 9;          // token row
    int i = idx & 511;         // feature
    int s = m & (SEQ-1);       // position within sequence
    int tok = tokens[m];
    float inv = powf(10000.0f, -(float)i * (1.0f/512.0f));
    float ang = (float)s * inv;
    float pe  = (i & 1) ? cosf(ang) : sinf(ang);
    x[idx] = emb[(size_t)tok * DMODEL + i] + pe;
}

// ---------------- GEMM: C[M,N] = A[M,K] @ B[K,N] + bias, optional ReLU ----
// BM=128, BN=64, BK=16, 256 threads, per-thread 8x4 micro-tile,
// accumulated as packed f32x2 pairs (2x FP32 rate on sm_103a).
__global__ __launch_bounds__(256)
void gemm_bias_kernel(const float* __restrict__ A,
                      const float* __restrict__ B,
                      const float* __restrict__ bias,
                      float* __restrict__ C,
                      int M, int N, int K, int doRelu)
{
    __shared__ float As[16][128];
    __shared__ float Bs[16][64];

    const int tid = threadIdx.x;
    const int bm  = blockIdx.y * 128;
    const int bn  = blockIdx.x * 64;
    const int tx  = tid & 15;     // N direction, 4 cols
    const int ty  = tid >> 4;     // M direction, 8 rows

    unsigned long long acc[8][2];
#pragma unroll
    for (int i = 0; i < 8; i++) { acc[i][0] = 0ULL; acc[i][1] = 0ULL; }

    const float* Ab = A + (size_t)bm * K;
    const float* Bb = B + bn;

    for (int k0 = 0; k0 < K; k0 += 16) {
        // A tile: 128 rows x 16 cols = 512 float4, 2 per thread (store transposed)
#pragma unroll
        for (int i = 0; i < 2; i++) {
            int f  = tid + i*256;
            int r  = f >> 2;
            int c4 = f & 3;
            float4 v = *(const float4*)(Ab + (size_t)r * K + k0 + c4*4);
            As[c4*4+0][r] = v.x;
            As[c4*4+1][r] = v.y;
            As[c4*4+2][r] = v.z;
            As[c4*4+3][r] = v.w;
        }
        // B tile: 16 rows x 64 cols = 256 float4, 1 per thread
        {
            int r  = tid >> 4;
            int c4 = tid & 15;
            float4 v = *(const float4*)(Bb + (size_t)(k0 + r) * N + c4*4);
            *(float4*)&Bs[r][c4*4] = v;
        }
        __syncthreads();

#pragma unroll
        for (int k = 0; k < 16; k++) {
            float4 a0 = *(const float4*)&As[k][ty*8];
            float4 a1 = *(const float4*)&As[k][ty*8+4];
            unsigned long long b0 = *(const unsigned long long*)&Bs[k][tx*4];
            unsigned long long b1 = *(const unsigned long long*)&Bs[k][tx*4+2];
            float av[8] = {a0.x, a0.y, a0.z, a0.w, a1.x, a1.y, a1.z, a1.w};
#pragma unroll
            for (int i = 0; i < 8; i++) {
                unsigned long long ap = pack2(av[i], av[i]);
                ffma2(acc[i][0], ap, b0);
                ffma2(acc[i][1], ap, b1);
            }
        }
        __syncthreads();
    }

    // epilogue: bias (+ReLU) and store
    float4 bb = *(const float4*)(bias + bn + tx*4);
#pragma unroll
    for (int i = 0; i < 8; i++) {
        float2 c0 = unpack2(acc[i][0]);
        float2 c1 = unpack2(acc[i][1]);
        float4 o;
        o.x = c0.x + bb.x;
        o.y = c0.y + bb.y;
        o.z = c1.x + bb.z;
        o.w = c1.y + bb.w;
        if (doRelu) {
            o.x = fmaxf(o.x, 0.f); o.y = fmaxf(o.y, 0.f);
            o.z = fmaxf(o.z, 0.f); o.w = fmaxf(o.w, 0.f);
        }
        *(float4*)(C + (size_t)(bm + ty*8 + i) * N + bn + tx*4) = o;
    }
}

// ---------------- flash-style attention, fp32, online softmax -----------
// grid: (SEQ/64, BATCH*NHEADS), block: 256 threads (8 warps, 8 q-rows/warp)
// Writes the output with the reference's head-interleave "bug":
//   out[b, h*128 + s/8, (s%8)*64 + d] = attn[b,h,s,d]
__global__ __launch_bounds__(256)
void attention_kernel(const float* __restrict__ Q,
                      const float* __restrict__ K,
                      const float* __restrict__ V,
                      float* __restrict__ O)
{
    const int bh   = blockIdx.y;
    const int b    = bh >> 3;
    const int h    = bh & 7;
    const int q0   = blockIdx.x * 64;
    const int tid  = threadIdx.x;
    const int warp = tid >> 5;
    const int lane = tid & 31;

    __shared__ float q_s[64][64];      // [qrow][d]
    __shared__ float k_s[32][65];      // [kcol][d], odd pad -> conflict-free
    __shared__ float v_s[32][64];      // [kcol][d]
    __shared__ float p_s[64][32];      // [qrow][kcol]

    const float* Qb = Q + ((size_t)b*SEQ + q0) * DMODEL + h*DHEAD;
    const float* Kb = K + ((size_t)b*SEQ) * DMODEL + h*DHEAD;
    const float* Vb = V + ((size_t)b*SEQ) * DMODEL + h*DHEAD;

    // load Q tile: 64 rows x 16 float4 = 1024 float4, 4 per thread
#pragma unroll
    for (int i = 0; i < 4; i++) {
        int f  = tid + i*256;
        int r  = f >> 4;
        int c4 = f & 15;
        float4 v = *(const float4*)(Qb + (size_t)r * DMODEL + c4*4);
        *(float4*)&q_s[r][c4*4] = v;
    }

    float m_i[8], l_i[8], o0[8], o1[8];
#pragma unroll
    for (int i = 0; i < 8; i++) { m_i[i] = -1e30f; l_i[i] = 0.f; o0[i] = 0.f; o1[i] = 0.f; }

    for (int t = 0; t < SEQ/32; t++) {
        __syncthreads();   // covers q_s first iter + smem reuse across iters
        // load K,V tiles: 32 rows x 16 float4 each -> 1024 total, 4 per thread
#pragma unroll
        for (int i = 0; i < 2; i++) {
            int f  = tid + i*256;
            int r  = f >> 4;
            int c4 = f & 15;
            float4 kv = *(const float4*)(Kb + (size_t)(t*32 + r) * DMODEL + c4*4);
            k_s[r][c4*4+0] = kv.x; k_s[r][c4*4+1] = kv.y;
            k_s[r][c4*4+2] = kv.z; k_s[r][c4*4+3] = kv.w;
            float4 vv = *(const float4*)(Vb + (size_t)(t*32 + r) * DMODEL + c4*4);
            *(float4*)&v_s[r][c4*4] = vv;
        }
        __syncthreads();

#pragma unroll
        for (int i = 0; i < 8; i++) {
            const int row = warp*8 + i;
            const float* qr = q_s[row];
            const float* kr = k_s[lane];
            float s0 = 0.f, s1 = 0.f, s2 = 0.f, s3 = 0.f;
#pragma unroll
            for (int d = 0; d < 64; d += 4) {
                s0 = fmaf(qr[d+0], kr[d+0], s0);
                s1 = fmaf(qr[d+1], kr[d+1], s1);
                s2 = fmaf(qr[d+2], kr[d+2], s2);
                s3 = fmaf(qr[d+3], kr[d+3], s3);
            }
            float s = ((s0 + s1) + (s2 + s3)) * 0.125f;   // 1/sqrt(64)

            float mt = s;
#pragma unroll
            for (int off = 16; off > 0; off >>= 1)
                mt = fmaxf(mt, __shfl_xor_sync(0xffffffffu, mt, off));
            float mnew  = fmaxf(m_i[i], mt);
            float p     = __expf(s - mnew);
            float alpha = __expf(m_i[i] - mnew);
            m_i[i] = mnew;
            float ps = p;
#pragma unroll
            for (int off = 16; off > 0; off >>= 1)
                ps += __shfl_xor_sync(0xffffffffu, ps, off);
            l_i[i] = l_i[i]*alpha + ps;
            o0[i] *= alpha; o1[i] *= alpha;

            p_s[row][lane] = p;
            __syncwarp();

            float a0 = 0.f, a1 = 0.f, b0 = 0.f, b1 = 0.f;
#pragma unroll
            for (int kk = 0; kk < 32; kk += 2) {
                float pk0 = p_s[row][kk];
                float2 v0 = *(const float2*)&v_s[kk][lane*2];
                a0 = fmaf(pk0, v0.x, a0);
                a1 = fmaf(pk0, v0.y, a1);
                float pk1 = p_s[row][kk+1];
                float2 v1 = *(const float2*)&v_s[kk+1][lane*2];
                b0 = fmaf(pk1, v1.x, b0);
                b1 = fmaf(pk1, v1.y, b1);
            }
            o0[i] += a0 + b0;
            o1[i] += a1 + b1;
        }
    }

    // epilogue: normalize and write with the reference reshape permutation
#pragma unroll
    for (int i = 0; i < 8; i++) {
        int row = warp*8 + i;
        int s   = q0 + row;
        float inv = 1.0f / l_i[i];
        size_t base = ((size_t)b*SEQ + h*128 + (s >> 3)) * DMODEL + (s & 7)*64 + lane*2;
        O[base]     = o0[i] * inv;
        O[base + 1] = o1[i] * inv;
    }
}

// ---------------- fused residual add + LayerNorm -------------------------
// out[row] = LN(x[row] + y[row]) * g + b ; one warp per 512-wide row
__global__ __launch_bounds__(256)
void resln_kernel(const float* __restrict__ x,
                  const float* __restrict__ y,
                  const float* __restrict__ g,
                  const float* __restrict__ bb,
                  float* __restrict__ out)
{
    int row  = blockIdx.x * 8 + (threadIdx.x >> 5);
    int lane = threadIdx.x & 31;
    const float4* xr = (const float4*)(x + (size_t)row * DMODEL);
    const float4* yr = (const float4*)(y + (size_t)row * DMODEL);

    float4 v[4];
    float s = 0.f;
#pragma unroll
    for (int j = 0; j < 4; j++) {
        float4 a = xr[lane + 32*j];
        float4 c = yr[lane + 32*j];
        v[j].x = a.x + c.x; v[j].y = a.y + c.y;
        v[j].z = a.z + c.z; v[j].w = a.w + c.w;
        s += (v[j].x + v[j].y) + (v[j].z + v[j].w);
    }
#pragma unroll
    for (int off = 16; off > 0; off >>= 1)
        s += __shfl_xor_sync(0xffffffffu, s, off);
    float mean = s * (1.0f/512.0f);

    float var = 0.f;
#pragma unroll
    for (int j = 0; j < 4; j++) {
        float dx = v[j].x - mean, dy = v[j].y - mean;
        float dz = v[j].z - mean, dw = v[j].w - mean;
        var += (dx*dx + dy*dy) + (dz*dz + dw*dw);
    }
#pragma unroll
    for (int off = 16; off > 0; off >>= 1)
        var += __shfl_xor_sync(0xffffffffu, var, off);
    var *= (1.0f/512.0f);
    float rstd = rsqrtf(var + LN_EPS);

    float4* orow = (float4*)(out + (size_t)row * DMODEL);
#pragma unroll
    for (int j = 0; j < 4; j++) {
        int col = (lane + 32*j) * 4;
        float4 gg = *(const float4*)(g  + col);
        float4 bv = *(const float4*)(bb + col);
        float4 o;
        o.x = (v[j].x - mean) * rstd * gg.x + bv.x;
        o.y = (v[j].y - mean) * rstd * gg.y + bv.y;
        o.z = (v[j].z - mean) * rstd * gg.z + bv.z;
        o.w = (v[j].w - mean) * rstd * gg.w + bv.w;
        orow[lane + 32*j] = o;
    }
}

// ---------------- host driver ----------------
extern "C" void kernel_launch(void* const* d_in, const int* in_sizes, int n_in,
                              void* d_out, int out_size)
{
    (void)in_sizes; (void)n_in; (void)out_size;

    const int*   tokens = (const int*)  d_in[0];
    const float* emb    = (const float*)d_in[1];
    const float* Wq     = (const float*)d_in[2];
    const float* bq     = (const float*)d_in[3];
    const float* Wk     = (const float*)d_in[4];
    const float* bk     = (const float*)d_in[5];
    const float* Wv     = (const float*)d_in[6];
    const float* bv     = (const float*)d_in[7];
    const float* Wo     = (const float*)d_in[8];
    const float* bo     = (const float*)d_in[9];
    const float* W1     = (const float*)d_in[10];
    const float* b1     = (const float*)d_in[11];
    const float* W2     = (const float*)d_in[12];
    const float* b2     = (const float*)d_in[13];
    const float* ln_g   = (const float*)d_in[14];
    const float* ln_b   = (const float*)d_in[15];

    float *x, *q, *k, *v, *attn, *tmp, *h1;
    cudaGetSymbolAddress((void**)&x,    g_x);
    cudaGetSymbolAddress((void**)&q,    g_q);
    cudaGetSymbolAddress((void**)&k,    g_k);
    cudaGetSymbolAddress((void**)&v,    g_v);
    cudaGetSymbolAddress((void**)&attn, g_attn);
    cudaGetSymbolAddress((void**)&tmp,  g_tmp);
    cudaGetSymbolAddress((void**)&h1,   g_h1);

    embed_kernel<<<(MTOK*DMODEL)/256, 256>>>(tokens, emb, x);

    dim3 gProj(DMODEL/64, MTOK/128);   // (8, 32)  for N=512
    dim3 gFF1 (FFDIM/64,  MTOK/128);   // (32, 32) for N=2048
    dim3 gAttn(SEQ/64, BATCH*NHEADS);  // (16, 32)

    for (int l = 0; l < NLAYER; l++) {
        const float* wq = Wq + (size_t)l*DMODEL*DMODEL;
        const float* wk = Wk + (size_t)l*DMODEL*DMODEL;
        const float* wv = Wv + (size_t)l*DMODEL*DMODEL;
        const float* wo = Wo + (size_t)l*DMODEL*DMODEL;
        const float* w1 = W1 + (size_t)l*DMODEL*FFDIM;
        const float* w2 = W2 + (size_t)l*FFDIM*DMODEL;

        gemm_bias_kernel<<<gProj, 256>>>(x, wq, bq + l*DMODEL, q, MTOK, DMODEL, DMODEL, 0);
        gemm_bias_kernel<<<gProj, 256>>>(x, wk, bk + l*DMODEL, k, MTOK, DMODEL, DMODEL, 0);
        gemm_bias_kernel<<<gProj, 256>>>(x, wv, bv + l*DMODEL, v, MTOK, DMODEL, DMODEL, 0);

        attention_kernel<<<gAttn, 256>>>(q, k, v, attn);

        gemm_bias_kernel<<<gProj, 256>>>(attn, wo, bo + l*DMODEL, tmp, MTOK, DMODEL, DMODEL, 0);
        resln_kernel<<<MTOK/8, 256>>>(x, tmp, ln_g + l*DMODEL, ln_b + l*DMODEL, x);

        gemm_bias_kernel<<<gFF1, 256>>>(x, w1, b1 + l*FFDIM, h1, MTOK, FFDIM, DMODEL, 1);
        gemm_bias_kernel<<<gProj, 256>>>(h1, w2, b2 + l*DMODEL, tmp, MTOK, DMODEL, FFDIM, 0);

        float* dst = (l == NLAYER-1) ? (float*)d_out : x;
        resln_kernel<<<MTOK/8, 256>>>(x, tmp, ln_g + l*DMODEL, ln_b + l*DMODEL, dst);
    }
}

// round 5
// speedup vs baseline: 1.7961x; 1.7961x over previous
#include <cuda_runtime.h>
#include <cstdint>
#include <math.h>

// ---------------- problem constants ----------------
#define BATCH   4
#define SEQ     1024
#define MTOK    (BATCH*SEQ)      // 4096
#define DMODEL  512
#define NHEADS  8
#define DHEAD   64
#define FFDIM   2048
#define NLAYER  6
#define LN_EPS  1e-5f

// ---------------- scratch (no allocation allowed) ----------------
__device__ float g_x   [MTOK*DMODEL];
__device__ float g_q   [MTOK*DMODEL];
__device__ float g_k   [MTOK*DMODEL];
__device__ float g_v   [MTOK*DMODEL];
__device__ float g_attn[MTOK*DMODEL];
__device__ float g_tmp [MTOK*DMODEL];
__device__ float g_h1  [MTOK*FFDIM];

// ---------------- packed f32x2 helpers (Blackwell FFMA2) ----------------
__device__ __forceinline__ unsigned long long pack2(float x, float y) {
    unsigned long long r;
    asm("mov.b64 %0, {%1, %2};" : "=l"(r) : "f"(x), "f"(y));
    return r;
}
__device__ __forceinline__ float2 unpack2(unsigned long long v) {
    float2 r;
    asm("mov.b64 {%0, %1}, %2;" : "=f"(r.x), "=f"(r.y) : "l"(v));
    return r;
}
__device__ __forceinline__ void ffma2(unsigned long long& d,
                                      unsigned long long a,
                                      unsigned long long b) {
    asm("fma.rn.f32x2 %0, %1, %2, %0;" : "+l"(d) : "l"(a), "l"(b));
}
__device__ __forceinline__ void fmul2(unsigned long long& d, unsigned long long a) {
    asm("mul.rn.f32x2 %0, %0, %1;" : "+l"(d) : "l"(a));
}

// ---------------- tf32 helpers ----------------
__device__ __forceinline__ uint32_t f2tf32(float x) {
    uint32_t r; asm("cvt.rna.tf32.f32 %0, %1;" : "=r"(r) : "f"(x)); return r;
}
__device__ __forceinline__ void mma_tf32(float c[4], const uint32_t a[4], const uint32_t b[2]) {
    asm volatile("mma.sync.aligned.m16n8k8.row.col.f32.tf32.tf32.f32 "
        "{%0,%1,%2,%3}, {%4,%5,%6,%7}, {%8,%9}, {%0,%1,%2,%3};"
        : "+f"(c[0]), "+f"(c[1]), "+f"(c[2]), "+f"(c[3])
        : "r"(a[0]), "r"(a[1]), "r"(a[2]), "r"(a[3]), "r"(b[0]), "r"(b[1]));
}

// ---------------- embedding + sinusoidal positional encoding ----------------
__global__ __launch_bounds__(256)
void embed_kernel(const int* __restrict__ tokens,
                  const float* __restrict__ emb,
                  float* __restrict__ x)
{
    int idx = blockIdx.x * blockDim.x + threadIdx.x;   // over MTOK*DMODEL
    if (idx >= MTOK*DMODEL) return;
    int m = idx >> 9;          // token row
    int i = idx & 511;         // feature
    int s = m & (SEQ-1);       // position within sequence
    int tok = tokens[m];
    float inv = powf(10000.0f, -(float)i * (1.0f/512.0f));
    float ang = (float)s * inv;
    float pe  = (i & 1) ? cosf(ang) : sinf(ang);
    x[idx] = emb[(size_t)tok * DMODEL + i] + pe;
}

// ---------------- tf32 tensor-core GEMM -----------------------------------
// C[M,N] = A[M,K] @ B[K,N] + bias, optional ReLU.
// Block 128x64, BK=16, 128 threads (4 warps as 2x2, warp tile 64x32),
// mma.sync.m16n8k8 tf32, double-buffered smem, rna conversion on staging.
#define AS_STRIDE 20    // 16 k-cols + pad -> conflict-free fragment loads
#define BS_STRIDE 72    // 64 n-cols + pad -> conflict-free fragment loads

__device__ __forceinline__ void gemm_stage_load(
    const float* __restrict__ Ab, const float* __restrict__ Bb,
    int K, int N, int k0, int tid, float4 a_st[4], float4 b_st[2])
{
#pragma unroll
    for (int i = 0; i < 4; i++) {
        int f = tid + i*128;
        int r = f >> 2, c4 = f & 3;
        a_st[i] = *(const float4*)(Ab + (size_t)r * K + k0 + c4*4);
    }
#pragma unroll
    for (int i = 0; i < 2; i++) {
        int f = tid + i*128;
        int r = f >> 4, c4 = f & 15;
        b_st[i] = *(const float4*)(Bb + (size_t)(k0 + r) * N + c4*4);
    }
}

__device__ __forceinline__ void gemm_stage_store(
    uint32_t* __restrict__ As, uint32_t* __restrict__ Bs,
    int tid, const float4 a_st[4], const float4 b_st[2])
{
#pragma unroll
    for (int i = 0; i < 4; i++) {
        int f = tid + i*128;
        int r = f >> 2, c4 = f & 3;
        uint32_t* p = As + r*AS_STRIDE + c4*4;
        p[0] = f2tf32(a_st[i].x);
        p[1] = f2tf32(a_st[i].y);
        p[2] = f2tf32(a_st[i].z);
        p[3] = f2tf32(a_st[i].w);
    }
#pragma unroll
    for (int i = 0; i < 2; i++) {
        int f = tid + i*128;
        int r = f >> 4, c4 = f & 15;
        uint4 u;
        u.x = f2tf32(b_st[i].x);
        u.y = f2tf32(b_st[i].y);
        u.z = f2tf32(b_st[i].z);
        u.w = f2tf32(b_st[i].w);
        *(uint4*)(Bs + r*BS_STRIDE + c4*4) = u;
    }
}

__global__ __launch_bounds__(128)
void gemm_tf32_kernel(const float* __restrict__ A,
                      const float* __restrict__ B,
                      const float* __restrict__ bias,
                      float* __restrict__ C,
                      int M, int N, int K, int doRelu)
{
    __shared__ uint32_t As[2][128*AS_STRIDE];
    __shared__ uint32_t Bs[2][16*BS_STRIDE];

    const int tid   = threadIdx.x;
    const int lane  = tid & 31;
    const int warp  = tid >> 5;
    const int warpM = warp >> 1;     // 0..1  -> 64-row half
    const int warpN = warp & 1;      // 0..1  -> 32-col half
    const int bm    = blockIdx.y * 128;
    const int bn    = blockIdx.x * 64;
    const int g     = lane >> 2;     // 0..7
    const int tg    = lane & 3;      // 0..3

    float acc[4][4][4];
#pragma unroll
    for (int mi = 0; mi < 4; mi++)
#pragma unroll
        for (int ni = 0; ni < 4; ni++)
#pragma unroll
            for (int j = 0; j < 4; j++) acc[mi][ni][j] = 0.f;

    const float* Ab = A + (size_t)bm * K;
    const float* Bb = B + bn;

    float4 a_st[4]; float4 b_st[2];
    gemm_stage_load(Ab, Bb, K, N, 0, tid, a_st, b_st);
    gemm_stage_store(As[0], Bs[0], tid, a_st, b_st);
    __syncthreads();

    int buf = 0;
    for (int k0 = 0; k0 < K; k0 += 16) {
        const bool more = (k0 + 16 < K);
        if (more) gemm_stage_load(Ab, Bb, K, N, k0 + 16, tid, a_st, b_st);

        const uint32_t* Ab_s = As[buf];
        const uint32_t* Bb_s = Bs[buf];
#pragma unroll
        for (int ks = 0; ks < 2; ks++) {
            uint32_t afr[4][4], bfr[4][2];
#pragma unroll
            for (int mi = 0; mi < 4; mi++) {
                const uint32_t* p = Ab_s + (warpM*64 + mi*16 + g)*AS_STRIDE + ks*8 + tg;
                afr[mi][0] = p[0];
                afr[mi][1] = p[8*AS_STRIDE];
                afr[mi][2] = p[4];
                afr[mi][3] = p[8*AS_STRIDE + 4];
            }
#pragma unroll
            for (int ni = 0; ni < 4; ni++) {
                const uint32_t* p = Bb_s + (ks*8 + tg)*BS_STRIDE + warpN*32 + ni*8 + g;
                bfr[ni][0] = p[0];
                bfr[ni][1] = p[4*BS_STRIDE];
            }
#pragma unroll
            for (int mi = 0; mi < 4; mi++)
#pragma unroll
                for (int ni = 0; ni < 4; ni++)
                    mma_tf32(acc[mi][ni], afr[mi], bfr[ni]);
        }

        if (more) gemm_stage_store(As[buf^1], Bs[buf^1], tid, a_st, b_st);
        __syncthreads();
        buf ^= 1;
    }

    // epilogue: bias (+ReLU), float2 stores
#pragma unroll
    for (int mi = 0; mi < 4; mi++) {
        int r0 = bm + warpM*64 + mi*16 + g;
#pragma unroll
        for (int ni = 0; ni < 4; ni++) {
            int c0 = bn + warpN*32 + ni*8 + tg*2;
            float2 bb = *(const float2*)(bias + c0);
            float2 o0, o1;
            o0.x = acc[mi][ni][0] + bb.x;
            o0.y = acc[mi][ni][1] + bb.y;
            o1.x = acc[mi][ni][2] + bb.x;
            o1.y = acc[mi][ni][3] + bb.y;
            if (doRelu) {
                o0.x = fmaxf(o0.x, 0.f); o0.y = fmaxf(o0.y, 0.f);
                o1.x = fmaxf(o1.x, 0.f); o1.y = fmaxf(o1.y, 0.f);
            }
            *(float2*)(C + (size_t)r0     * N + c0) = o0;
            *(float2*)(C + (size_t)(r0+8) * N + c0) = o1;
        }
    }
}

// ---------------- flash-style attention, fp32 + packed f32x2 -------------
// grid: (SEQ/64, BATCH*NHEADS), block: 256 threads (8 warps, 8 q-rows/warp).
// Per 32-key tile each lane owns one key; its K vector is cached in registers
// as 32 packed f32x2 pairs and reused across the warp's 8 q-rows.
// Writes output with the reference's head-interleave reshape:
//   out[b, h*128 + s/8, (s%8)*64 + d] = attn[b,h,s,d]
__global__ __launch_bounds__(256)
void attention_kernel(const float* __restrict__ Q,
                      const float* __restrict__ K,
                      const float* __restrict__ V,
                      float* __restrict__ O)
{
    const int bh   = blockIdx.y;
    const int b    = bh >> 3;
    const int h    = bh & 7;
    const int q0   = blockIdx.x * 64;
    const int tid  = threadIdx.x;
    const int warp = tid >> 5;
    const int lane = tid & 31;

    __shared__ float q_s[64][64];      // [qrow][d]   (stride 64, float2-friendly)
    __shared__ float k_s[32][66];      // [kcol][d]   (even pad for float2 loads)
    __shared__ float v_s[32][64];      // [kcol][d]
    __shared__ float p_s[64][32];      // [qrow][kcol]

    const float* Qb = Q + ((size_t)b*SEQ + q0) * DMODEL + h*DHEAD;
    const float* Kb = K + ((size_t)b*SEQ) * DMODEL + h*DHEAD;
    const float* Vb = V + ((size_t)b*SEQ) * DMODEL + h*DHEAD;

    // load Q tile: 64 rows x 16 float4 = 1024 float4, 4 per thread
#pragma unroll
    for (int i = 0; i < 4; i++) {
        int f  = tid + i*256;
        int r  = f >> 4;
        int c4 = f & 15;
        float4 v = *(const float4*)(Qb + (size_t)r * DMODEL + c4*4);
        *(float4*)&q_s[r][c4*4] = v;
    }

    float m_i[8], l_i[8];
    unsigned long long o_acc[8];
#pragma unroll
    for (int i = 0; i < 8; i++) { m_i[i] = -1e30f; l_i[i] = 0.f; o_acc[i] = 0ULL; }

    for (int t = 0; t < SEQ/32; t++) {
        __syncthreads();   // covers q_s first iter + smem reuse across iters
        // load K,V tiles: 32 rows x 16 float4 each, 4 per thread
#pragma unroll
        for (int i = 0; i < 2; i++) {
            int f  = tid + i*256;
            int r  = f >> 4;
            int c4 = f & 15;
            float4 kv = *(const float4*)(Kb + (size_t)(t*32 + r) * DMODEL + c4*4);
            k_s[r][c4*4+0] = kv.x; k_s[r][c4*4+1] = kv.y;
            k_s[r][c4*4+2] = kv.z; k_s[r][c4*4+3] = kv.w;
            float4 vv = *(const float4*)(Vb + (size_t)(t*32 + r) * DMODEL + c4*4);
            *(float4*)&v_s[r][c4*4] = vv;
        }
        __syncthreads();

        // cache this lane's key vector in registers (32 x f32x2)
        unsigned long long kreg[32];
#pragma unroll
        for (int d = 0; d < 32; d++)
            kreg[d] = *(const unsigned long long*)&k_s[lane][2*d];

#pragma unroll
        for (int i = 0; i < 8; i++) {
            const int row = warp*8 + i;
            // score: dot(q_row, k_lane), two packed accumulator chains
            unsigned long long sA = 0ULL, sB = 0ULL;
#pragma unroll
            for (int d = 0; d < 32; d += 2) {
                unsigned long long qa = *(const unsigned long long*)&q_s[row][2*d];
                unsigned long long qb = *(const unsigned long long*)&q_s[row][2*d+2];
                ffma2(sA, qa, kreg[d]);
                ffma2(sB, qb, kreg[d+1]);
            }
            float2 pa = unpack2(sA), pb = unpack2(sB);
            float s = ((pa.x + pa.y) + (pb.x + pb.y)) * 0.125f;   // 1/sqrt(64)

            float mt = s;
#pragma unroll
            for (int off = 16; off > 0; off >>= 1)
                mt = fmaxf(mt, __shfl_xor_sync(0xffffffffu, mt, off));
            float mnew  = fmaxf(m_i[i], mt);
            float p     = __expf(s - mnew);
            float alpha = __expf(m_i[i] - mnew);
            m_i[i] = mnew;
            float ps = p;
#pragma unroll
            for (int off = 16; off > 0; off >>= 1)
                ps += __shfl_xor_sync(0xffffffffu, ps, off);
            l_i[i] = l_i[i]*alpha + ps;
            fmul2(o_acc[i], pack2(alpha, alpha));

            p_s[row][lane] = p;
            __syncwarp();

            // PV: packed accumulate over 32 keys, 2 temp chains
            unsigned long long oa = 0ULL, ob = 0ULL;
#pragma unroll
            for (int kk = 0; kk < 32; kk += 2) {
                float pk0 = p_s[row][kk];
                unsigned long long v0 = *(const unsigned long long*)&v_s[kk][lane*2];
                ffma2(oa, pack2(pk0, pk0), v0);
                float pk1 = p_s[row][kk+1];
                unsigned long long v1 = *(const unsigned long long*)&v_s[kk+1][lane*2];
                ffma2(ob, pack2(pk1, pk1), v1);
            }
            float2 fa = unpack2(oa), fb = unpack2(ob);
            float2 fo = unpack2(o_acc[i]);
            fo.x += fa.x + fb.x;
            fo.y += fa.y + fb.y;
            o_acc[i] = pack2(fo.x, fo.y);
        }
    }

    // epilogue: normalize and write with the reference reshape permutation
#pragma unroll
    for (int i = 0; i < 8; i++) {
        int row = warp*8 + i;
        int s   = q0 + row;
        float inv = 1.0f / l_i[i];
        float2 fo = unpack2(o_acc[i]);
        size_t base = ((size_t)b*SEQ + h*128 + (s >> 3)) * DMODEL + (s & 7)*64 + lane*2;
        O[base]     = fo.x * inv;
        O[base + 1] = fo.y * inv;
    }
}

// ---------------- fused residual add + LayerNorm -------------------------
// out[row] = LN(x[row] + y[row]) * g + b ; one warp per 512-wide row
__global__ __launch_bounds__(256)
void resln_kernel(const float* __restrict__ x,
                  const float* __restrict__ y,
                  const float* __restrict__ g,
                  const float* __restrict__ bb,
                  float* __restrict__ out)
{
    int row  = blockIdx.x * 8 + (threadIdx.x >> 5);
    int lane = threadIdx.x & 31;
    const float4* xr = (const float4*)(x + (size_t)row * DMODEL);
    const float4* yr = (const float4*)(y + (size_t)row * DMODEL);

    float4 v[4];
    float s = 0.f;
#pragma unroll
    for (int j = 0; j < 4; j++) {
        float4 a = xr[lane + 32*j];
        float4 c = yr[lane + 32*j];
        v[j].x = a.x + c.x; v[j].y = a.y + c.y;
        v[j].z = a.z + c.z; v[j].w = a.w + c.w;
        s += (v[j].x + v[j].y) + (v[j].z + v[j].w);
    }
#pragma unroll
    for (int off = 16; off > 0; off >>= 1)
        s += __shfl_xor_sync(0xffffffffu, s, off);
    float mean = s * (1.0f/512.0f);

    float var = 0.f;
#pragma unroll
    for (int j = 0; j < 4; j++) {
        float dx = v[j].x - mean, dy = v[j].y - mean;
        float dz = v[j].z - mean, dw = v[j].w - mean;
        var += (dx*dx + dy*dy) + (dz*dz + dw*dw);
    }
#pragma unroll
    for (int off = 16; off > 0; off >>= 1)
        var += __shfl_xor_sync(0xffffffffu, var, off);
    var *= (1.0f/512.0f);
    float rstd = rsqrtf(var + LN_EPS);

    float4* orow = (float4*)(out + (size_t)row * DMODEL);
#pragma unroll
    for (int j = 0; j < 4; j++) {
        int col = (lane + 32*j) * 4;
        float4 gg = *(const float4*)(g  + col);
        float4 bv = *(const float4*)(bb + col);
        float4 o;
        o.x = (v[j].x - mean) * rstd * gg.x + bv.x;
        o.y = (v[j].y - mean) * rstd * gg.y + bv.y;
        o.z = (v[j].z - mean) * rstd * gg.z + bv.z;
        o.w = (v[j].w - mean) * rstd * gg.w + bv.w;
        orow[lane + 32*j] = o;
    }
}

// ---------------- host driver ----------------
extern "C" void kernel_launch(void* const* d_in, const int* in_sizes, int n_in,
                              void* d_out, int out_size)
{
    (void)in_sizes; (void)n_in; (void)out_size;

    const int*   tokens = (const int*)  d_in[0];
    const float* emb    = (const float*)d_in[1];
    const float* Wq     = (const float*)d_in[2];
    const float* bq     = (const float*)d_in[3];
    const float* Wk     = (const float*)d_in[4];
    const float* bk     = (const float*)d_in[5];
    const float* Wv     = (const float*)d_in[6];
    const float* bv     = (const float*)d_in[7];
    const float* Wo     = (const float*)d_in[8];
    const float* bo     = (const float*)d_in[9];
    const float* W1     = (const float*)d_in[10];
    const float* b1     = (const float*)d_in[11];
    const float* W2     = (const float*)d_in[12];
    const float* b2     = (const float*)d_in[13];
    const float* ln_g   = (const float*)d_in[14];
    const float* ln_b   = (const float*)d_in[15];

    float *x, *q, *k, *v, *attn, *tmp, *h1;
    cudaGetSymbolAddress((void**)&x,    g_x);
    cudaGetSymbolAddress((void**)&q,    g_q);
    cudaGetSymbolAddress((void**)&k,    g_k);
    cudaGetSymbolAddress((void**)&v,    g_v);
    cudaGetSymbolAddress((void**)&attn, g_attn);
    cudaGetSymbolAddress((void**)&tmp,  g_tmp);
    cudaGetSymbolAddress((void**)&h1,   g_h1);

    embed_kernel<<<(MTOK*DMODEL)/256, 256>>>(tokens, emb, x);

    dim3 gProj(DMODEL/64, MTOK/128);   // (8, 32)  for N=512
    dim3 gFF1 (FFDIM/64,  MTOK/128);   // (32, 32) for N=2048
    dim3 gAttn(SEQ/64, BATCH*NHEADS);  // (16, 32)

    for (int l = 0; l < NLAYER; l++) {
        const float* wq = Wq + (size_t)l*DMODEL*DMODEL;
        const float* wk = Wk + (size_t)l*DMODEL*DMODEL;
        const float* wv = Wv + (size_t)l*DMODEL*DMODEL;
        const float* wo = Wo + (size_t)l*DMODEL*DMODEL;
        const float* w1 = W1 + (size_t)l*DMODEL*FFDIM;
        const float* w2 = W2 + (size_t)l*FFDIM*DMODEL;

        gemm_tf32_kernel<<<gProj, 128>>>(x, wq, bq + l*DMODEL, q, MTOK, DMODEL, DMODEL, 0);
        gemm_tf32_kernel<<<gProj, 128>>>(x, wk, bk + l*DMODEL, k, MTOK, DMODEL, DMODEL, 0);
        gemm_tf32_kernel<<<gProj, 128>>>(x, wv, bv + l*DMODEL, v, MTOK, DMODEL, DMODEL, 0);

        attention_kernel<<<gAttn, 256>>>(q, k, v, attn);

        gemm_tf32_kernel<<<gProj, 128>>>(attn, wo, bo + l*DMODEL, tmp, MTOK, DMODEL, DMODEL, 0);
        resln_kernel<<<MTOK/8, 256>>>(x, tmp, ln_g + l*DMODEL, ln_b + l*DMODEL, x);

        gemm_tf32_kernel<<<gFF1, 128>>>(x, w1, b1 + l*FFDIM, h1, MTOK, FFDIM, DMODEL, 1);
        gemm_tf32_kernel<<<gProj, 128>>>(h1, w2, b2 + l*DMODEL, tmp, MTOK, DMODEL, FFDIM, 0);

        float* dst = (l == NLAYER-1) ? (float*)d_out : x;
        resln_kernel<<<MTOK/8, 256>>>(x, tmp, ln_g + l*DMODEL, ln_b + l*DMODEL, dst);
    }
}

// round 6
// speedup vs baseline: 4.1212x; 2.2945x over previous
#include <cuda_runtime.h>
#include <cstdint>
#include <math.h>

// ---------------- problem constants ----------------
#define BATCH   4
#define SEQ     1024
#define MTOK    (BATCH*SEQ)      // 4096
#define DMODEL  512
#define NHEADS  8
#define DHEAD   64
#define FFDIM   2048
#define NLAYER  6
#define LN_EPS  1e-5f

// ---------------- scratch (no allocation allowed) ----------------
__device__ float g_x   [MTOK*DMODEL];
__device__ float g_q   [MTOK*DMODEL];
__device__ float g_k   [MTOK*DMODEL];
__device__ float g_v   [MTOK*DMODEL];
__device__ float g_attn[MTOK*DMODEL];
__device__ float g_tmp [MTOK*DMODEL];
__device__ float g_h1  [MTOK*FFDIM];

// ---------------- tf32 helpers ----------------
__device__ __forceinline__ uint32_t f2tf32(float x) {
    uint32_t r; asm("cvt.rna.tf32.f32 %0, %1;" : "=r"(r) : "f"(x)); return r;
}
__device__ __forceinline__ void mma_tf32(float c[4], const uint32_t a[4], const uint32_t b[2]) {
    asm volatile("mma.sync.aligned.m16n8k8.row.col.f32.tf32.tf32.f32 "
        "{%0,%1,%2,%3}, {%4,%5,%6,%7}, {%8,%9}, {%0,%1,%2,%3};"
        : "+f"(c[0]), "+f"(c[1]), "+f"(c[2]), "+f"(c[3])
        : "r"(a[0]), "r"(a[1]), "r"(a[2]), "r"(a[3]), "r"(b[0]), "r"(b[1]));
}

// ---------------- embedding + sinusoidal positional encoding ----------------
__global__ __launch_bounds__(256)
void embed_kernel(const int* __restrict__ tokens,
                  const float* __restrict__ emb,
                  float* __restrict__ x)
{
    int idx = blockIdx.x * blockDim.x + threadIdx.x;
    if (idx >= MTOK*DMODEL) return;
    int m = idx >> 9;
    int i = idx & 511;
    int s = m & (SEQ-1);
    int tok = tokens[m];
    float inv = powf(10000.0f, -(float)i * (1.0f/512.0f));
    float ang = (float)s * inv;
    float pe  = (i & 1) ? cosf(ang) : sinf(ang);
    x[idx] = emb[(size_t)tok * DMODEL + i] + pe;
}

// ---------------- tf32 tensor-core GEMM -----------------------------------
// C[M,N] = A[M,K] @ B[K,N] + bias, optional ReLU.
// Block 128x64, BK=16, 128 threads (4 warps as 2x2, warp tile 64x32),
// mma.sync.m16n8k8 tf32, double-buffered smem.
// gridDim.z selects among up to 3 (B, bias, C) sets (fused QKV).
#define AS_STRIDE 20
#define BS_STRIDE 72

struct GemmSet { const float* B; const float* bias; float* C; };

__device__ __forceinline__ void gemm_stage_load(
    const float* __restrict__ Ab, const float* __restrict__ Bb,
    int K, int N, int k0, int tid, float4 a_st[4], float4 b_st[2])
{
#pragma unroll
    for (int i = 0; i < 4; i++) {
        int f = tid + i*128;
        int r = f >> 2, c4 = f & 3;
        a_st[i] = *(const float4*)(Ab + (size_t)r * K + k0 + c4*4);
    }
#pragma unroll
    for (int i = 0; i < 2; i++) {
        int f = tid + i*128;
        int r = f >> 4, c4 = f & 15;
        b_st[i] = *(const float4*)(Bb + (size_t)(k0 + r) * N + c4*4);
    }
}

__device__ __forceinline__ void gemm_stage_store(
    uint32_t* __restrict__ As, uint32_t* __restrict__ Bs,
    int tid, const float4 a_st[4], const float4 b_st[2])
{
#pragma unroll
    for (int i = 0; i < 4; i++) {
        int f = tid + i*128;
        int r = f >> 2, c4 = f & 3;
        uint32_t* p = As + r*AS_STRIDE + c4*4;
        p[0] = f2tf32(a_st[i].x);
        p[1] = f2tf32(a_st[i].y);
        p[2] = f2tf32(a_st[i].z);
        p[3] = f2tf32(a_st[i].w);
    }
#pragma unroll
    for (int i = 0; i < 2; i++) {
        int f = tid + i*128;
        int r = f >> 4, c4 = f & 15;
        uint4 u;
        u.x = f2tf32(b_st[i].x);
        u.y = f2tf32(b_st[i].y);
        u.z = f2tf32(b_st[i].z);
        u.w = f2tf32(b_st[i].w);
        *(uint4*)(Bs + r*BS_STRIDE + c4*4) = u;
    }
}

__global__ __launch_bounds__(128)
void gemm_tf32_kernel(const float* __restrict__ A,
                      GemmSet s0, GemmSet s1, GemmSet s2,
                      int M, int N, int K, int doRelu)
{
    __shared__ uint32_t As[2][128*AS_STRIDE];
    __shared__ uint32_t Bs[2][16*BS_STRIDE];

    const int z = blockIdx.z;
    const GemmSet gs = (z == 0) ? s0 : (z == 1) ? s1 : s2;
    const float* B    = gs.B;
    const float* bias = gs.bias;
    float*       C    = gs.C;

    const int tid   = threadIdx.x;
    const int lane  = tid & 31;
    const int warp  = tid >> 5;
    const int warpM = warp >> 1;
    const int warpN = warp & 1;
    const int bm    = blockIdx.y * 128;
    const int bn    = blockIdx.x * 64;
    const int g     = lane >> 2;
    const int tg    = lane & 3;

    float acc[4][4][4];
#pragma unroll
    for (int mi = 0; mi < 4; mi++)
#pragma unroll
        for (int ni = 0; ni < 4; ni++)
#pragma unroll
            for (int j = 0; j < 4; j++) acc[mi][ni][j] = 0.f;

    const float* Ab = A + (size_t)bm * K;
    const float* Bb = B + bn;

    float4 a_st[4]; float4 b_st[2];
    gemm_stage_load(Ab, Bb, K, N, 0, tid, a_st, b_st);
    gemm_stage_store(As[0], Bs[0], tid, a_st, b_st);
    __syncthreads();

    int buf = 0;
    for (int k0 = 0; k0 < K; k0 += 16) {
        const bool more = (k0 + 16 < K);
        if (more) gemm_stage_load(Ab, Bb, K, N, k0 + 16, tid, a_st, b_st);

        const uint32_t* Ab_s = As[buf];
        const uint32_t* Bb_s = Bs[buf];
#pragma unroll
        for (int ks = 0; ks < 2; ks++) {
            uint32_t afr[4][4], bfr[4][2];
#pragma unroll
            for (int mi = 0; mi < 4; mi++) {
                const uint32_t* p = Ab_s + (warpM*64 + mi*16 + g)*AS_STRIDE + ks*8 + tg;
                afr[mi][0] = p[0];
                afr[mi][1] = p[8*AS_STRIDE];
                afr[mi][2] = p[4];
                afr[mi][3] = p[8*AS_STRIDE + 4];
            }
#pragma unroll
            for (int ni = 0; ni < 4; ni++) {
                const uint32_t* p = Bb_s + (ks*8 + tg)*BS_STRIDE + warpN*32 + ni*8 + g;
                bfr[ni][0] = p[0];
                bfr[ni][1] = p[4*BS_STRIDE];
            }
#pragma unroll
            for (int mi = 0; mi < 4; mi++)
#pragma unroll
                for (int ni = 0; ni < 4; ni++)
                    mma_tf32(acc[mi][ni], afr[mi], bfr[ni]);
        }

        if (more) gemm_stage_store(As[buf^1], Bs[buf^1], tid, a_st, b_st);
        __syncthreads();
        buf ^= 1;
    }

#pragma unroll
    for (int mi = 0; mi < 4; mi++) {
        int r0 = bm + warpM*64 + mi*16 + g;
#pragma unroll
        for (int ni = 0; ni < 4; ni++) {
            int c0 = bn + warpN*32 + ni*8 + tg*2;
            float2 bb = *(const float2*)(bias + c0);
            float2 o0, o1;
            o0.x = acc[mi][ni][0] + bb.x;
            o0.y = acc[mi][ni][1] + bb.y;
            o1.x = acc[mi][ni][2] + bb.x;
            o1.y = acc[mi][ni][3] + bb.y;
            if (doRelu) {
                o0.x = fmaxf(o0.x, 0.f); o0.y = fmaxf(o0.y, 0.f);
                o1.x = fmaxf(o1.x, 0.f); o1.y = fmaxf(o1.y, 0.f);
            }
            *(float2*)(C + (size_t)r0     * N + c0) = o0;
            *(float2*)(C + (size_t)(r0+8) * N + c0) = o1;
        }
    }
}

// ---------------- tensor-core flash attention (tf32 mma) ------------------
// grid: (SEQ/64, BATCH*NHEADS), 128 threads (4 warps, 16 q-rows each).
// Q pre-scaled by 0.125*log2(e): softmax in exp2 domain (raw MUFU.EX2).
// QK^T and P*V both mma.m16n8k8 tf32; P re-fragmented through smem.
// Output written with the reference head-interleave reshape:
//   out[b, h*128 + s/8, (s%8)*64 + d] = attn[b,h,s,d]
#define ATT_STRIDE 68
#define ATT_SMEM_BYTES (4 * 64 * ATT_STRIDE * 4)

__global__ __launch_bounds__(128)
void attn_mma_kernel(const float* __restrict__ Q,
                     const float* __restrict__ K,
                     const float* __restrict__ V,
                     float* __restrict__ O)
{
    extern __shared__ uint32_t att_s[];
    uint32_t* q_s = att_s;                       // [64][68]
    uint32_t* k_s = q_s + 64*ATT_STRIDE;
    uint32_t* v_s = k_s + 64*ATT_STRIDE;
    uint32_t* p_s = v_s + 64*ATT_STRIDE;

    const int bh   = blockIdx.y;
    const int b    = bh >> 3;
    const int h    = bh & 7;
    const int q0   = blockIdx.x * 64;
    const int tid  = threadIdx.x;
    const int warp = tid >> 5;
    const int lane = tid & 31;
    const int g    = lane >> 2;     // quad row
    const int t    = lane & 3;      // quad col
    const int wr   = warp * 16;     // warp row base

    const float* Qb = Q + ((size_t)b*SEQ + q0) * DMODEL + h*DHEAD;
    const float* Kb = K + ((size_t)b*SEQ) * DMODEL + h*DHEAD;
    const float* Vb = V + ((size_t)b*SEQ) * DMODEL + h*DHEAD;

    const float QSCALE = 0.125f * 1.4426950408889634f;   // 1/sqrt(64) * log2(e)

    // stage Q (scaled, tf32): 64x64 = 1024 float4, 8 per thread
#pragma unroll
    for (int i = 0; i < 8; i++) {
        int f  = tid + i*128;
        int r  = f >> 4;
        int c4 = f & 15;
        float4 v = *(const float4*)(Qb + (size_t)r * DMODEL + c4*4);
        uint32_t* p = q_s + r*ATT_STRIDE + c4*4;
        p[0] = f2tf32(v.x * QSCALE);
        p[1] = f2tf32(v.y * QSCALE);
        p[2] = f2tf32(v.z * QSCALE);
        p[3] = f2tf32(v.w * QSCALE);
    }

    float m_lo = -1e30f, m_hi = -1e30f, l_lo = 0.f, l_hi = 0.f;
    float o[8][4];
#pragma unroll
    for (int nt = 0; nt < 8; nt++)
#pragma unroll
        for (int j = 0; j < 4; j++) o[nt][j] = 0.f;

    for (int kt = 0; kt < SEQ/64; kt++) {
        __syncthreads();
        // stage K,V tiles (64x64 each, tf32)
#pragma unroll
        for (int i = 0; i < 8; i++) {
            int f  = tid + i*128;
            int r  = f >> 4;
            int c4 = f & 15;
            float4 kv = *(const float4*)(Kb + (size_t)(kt*64 + r) * DMODEL + c4*4);
            uint32_t* pk = k_s + r*ATT_STRIDE + c4*4;
            pk[0] = f2tf32(kv.x); pk[1] = f2tf32(kv.y);
            pk[2] = f2tf32(kv.z); pk[3] = f2tf32(kv.w);
            float4 vv = *(const float4*)(Vb + (size_t)(kt*64 + r) * DMODEL + c4*4);
            uint32_t* pv = v_s + r*ATT_STRIDE + c4*4;
            pv[0] = f2tf32(vv.x); pv[1] = f2tf32(vv.y);
            pv[2] = f2tf32(vv.z); pv[3] = f2tf32(vv.w);
        }
        __syncthreads();

        // ---- scores: S = Q K^T (64 keys), per-warp 16x64 in C fragments
        float c[8][4];
#pragma unroll
        for (int nt = 0; nt < 8; nt++)
#pragma unroll
            for (int j = 0; j < 4; j++) c[nt][j] = 0.f;

#pragma unroll
        for (int ks = 0; ks < 8; ks++) {
            uint32_t afr[4];
            const uint32_t* qa = q_s + (wr + g)*ATT_STRIDE + ks*8 + t;
            afr[0] = qa[0];
            afr[1] = qa[8*ATT_STRIDE];
            afr[2] = qa[4];
            afr[3] = qa[8*ATT_STRIDE + 4];
#pragma unroll
            for (int nt = 0; nt < 8; nt++) {
                uint32_t bfr[2];
                const uint32_t* kb = k_s + (nt*8 + g)*ATT_STRIDE + ks*8 + t;
                bfr[0] = kb[0];
                bfr[1] = kb[4];
                mma_tf32(c[nt], afr, bfr);
            }
        }

        // ---- online softmax (exp2 domain, scores already scaled)
        float mx_lo = c[0][0], mx_hi = c[0][2];
#pragma unroll
        for (int nt = 0; nt < 8; nt++) {
            mx_lo = fmaxf(mx_lo, fmaxf(c[nt][0], c[nt][1]));
            mx_hi = fmaxf(mx_hi, fmaxf(c[nt][2], c[nt][3]));
        }
        mx_lo = fmaxf(mx_lo, __shfl_xor_sync(0xffffffffu, mx_lo, 1));
        mx_lo = fmaxf(mx_lo, __shfl_xor_sync(0xffffffffu, mx_lo, 2));
        mx_hi = fmaxf(mx_hi, __shfl_xor_sync(0xffffffffu, mx_hi, 1));
        mx_hi = fmaxf(mx_hi, __shfl_xor_sync(0xffffffffu, mx_hi, 2));

        float mn_lo = fmaxf(m_lo, mx_lo);
        float mn_hi = fmaxf(m_hi, mx_hi);
        float alpha_lo = exp2f(m_lo - mn_lo);
        float alpha_hi = exp2f(m_hi - mn_hi);
        m_lo = mn_lo; m_hi = mn_hi;

        float sum_lo = 0.f, sum_hi = 0.f;
#pragma unroll
        for (int nt = 0; nt < 8; nt++) {
            c[nt][0] = exp2f(c[nt][0] - mn_lo);
            c[nt][1] = exp2f(c[nt][1] - mn_lo);
            c[nt][2] = exp2f(c[nt][2] - mn_hi);
            c[nt][3] = exp2f(c[nt][3] - mn_hi);
            sum_lo += c[nt][0] + c[nt][1];
            sum_hi += c[nt][2] + c[nt][3];
        }
        sum_lo += __shfl_xor_sync(0xffffffffu, sum_lo, 1);
        sum_lo += __shfl_xor_sync(0xffffffffu, sum_lo, 2);
        sum_hi += __shfl_xor_sync(0xffffffffu, sum_hi, 1);
        sum_hi += __shfl_xor_sync(0xffffffffu, sum_hi, 2);
        l_lo = l_lo*alpha_lo + sum_lo;
        l_hi = l_hi*alpha_hi + sum_hi;

        // ---- P -> smem (tf32), warp-private rows
#pragma unroll
        for (int nt = 0; nt < 8; nt++) {
            uint2 u0 = { f2tf32(c[nt][0]), f2tf32(c[nt][1]) };
            *(uint2*)(p_s + (wr + g)*ATT_STRIDE + nt*8 + 2*t) = u0;
            uint2 u1 = { f2tf32(c[nt][2]), f2tf32(c[nt][3]) };
            *(uint2*)(p_s + (wr + g + 8)*ATT_STRIDE + nt*8 + 2*t) = u1;
        }
        __syncwarp();

        // ---- rescale O accumulators
#pragma unroll
        for (int nt = 0; nt < 8; nt++) {
            o[nt][0] *= alpha_lo; o[nt][1] *= alpha_lo;
            o[nt][2] *= alpha_hi; o[nt][3] *= alpha_hi;
        }

        // ---- O += P V
#pragma unroll
        for (int ks = 0; ks < 8; ks++) {
            uint32_t afr[4];
            const uint32_t* pa = p_s + (wr + g)*ATT_STRIDE + ks*8 + t;
            afr[0] = pa[0];
            afr[1] = pa[8*ATT_STRIDE];
            afr[2] = pa[4];
            afr[3] = pa[8*ATT_STRIDE + 4];
#pragma unroll
            for (int nt = 0; nt < 8; nt++) {
                uint32_t bfr[2];
                const uint32_t* vb = v_s + (ks*8 + t)*ATT_STRIDE + nt*8 + g;
                bfr[0] = vb[0];
                bfr[1] = vb[4*ATT_STRIDE];
                mma_tf32(o[nt], afr, bfr);
            }
        }
    }

    // ---- epilogue: normalize, write with reshape permutation
    float inv_lo = 1.0f / l_lo;
    float inv_hi = 1.0f / l_hi;
    int s_lo = q0 + wr + g;
    int s_hi = s_lo + 8;
    size_t base_lo = ((size_t)b*SEQ + h*128 + (s_lo >> 3)) * DMODEL + (s_lo & 7)*64;
    size_t base_hi = ((size_t)b*SEQ + h*128 + (s_hi >> 3)) * DMODEL + (s_hi & 7)*64;
#pragma unroll
    for (int nt = 0; nt < 8; nt++) {
        int d = nt*8 + 2*t;
        float2 lo = { o[nt][0]*inv_lo, o[nt][1]*inv_lo };
        float2 hi = { o[nt][2]*inv_hi, o[nt][3]*inv_hi };
        *(float2*)(O + base_lo + d) = lo;
        *(float2*)(O + base_hi + d) = hi;
    }
}

// ---------------- fused residual add + LayerNorm -------------------------
__global__ __launch_bounds__(256)
void resln_kernel(const float* __restrict__ x,
                  const float* __restrict__ y,
                  const float* __restrict__ g,
                  const float* __restrict__ bb,
                  float* __restrict__ out)
{
    int row  = blockIdx.x * 8 + (threadIdx.x >> 5);
    int lane = threadIdx.x & 31;
    const float4* xr = (const float4*)(x + (size_t)row * DMODEL);
    const float4* yr = (const float4*)(y + (size_t)row * DMODEL);

    float4 v[4];
    float s = 0.f;
#pragma unroll
    for (int j = 0; j < 4; j++) {
        float4 a = xr[lane + 32*j];
        float4 c = yr[lane + 32*j];
        v[j].x = a.x + c.x; v[j].y = a.y + c.y;
        v[j].z = a.z + c.z; v[j].w = a.w + c.w;
        s += (v[j].x + v[j].y) + (v[j].z + v[j].w);
    }
#pragma unroll
    for (int off = 16; off > 0; off >>= 1)
        s += __shfl_xor_sync(0xffffffffu, s, off);
    float mean = s * (1.0f/512.0f);

    float var = 0.f;
#pragma unroll
    for (int j = 0; j < 4; j++) {
        float dx = v[j].x - mean, dy = v[j].y - mean;
        float dz = v[j].z - mean, dw = v[j].w - mean;
        var += (dx*dx + dy*dy) + (dz*dz + dw*dw);
    }
#pragma unroll
    for (int off = 16; off > 0; off >>= 1)
        var += __shfl_xor_sync(0xffffffffu, var, off);
    var *= (1.0f/512.0f);
    float rstd = rsqrtf(var + LN_EPS);

    float4* orow = (float4*)(out + (size_t)row * DMODEL);
#pragma unroll
    for (int j = 0; j < 4; j++) {
        int col = (lane + 32*j) * 4;
        float4 gg = *(const float4*)(g  + col);
        float4 bv = *(const float4*)(bb + col);
        float4 o;
        o.x = (v[j].x - mean) * rstd * gg.x + bv.x;
        o.y = (v[j].y - mean) * rstd * gg.y + bv.y;
        o.z = (v[j].z - mean) * rstd * gg.z + bv.z;
        o.w = (v[j].w - mean) * rstd * gg.w + bv.w;
        orow[lane + 32*j] = o;
    }
}

// ---------------- host driver ----------------
extern "C" void kernel_launch(void* const* d_in, const int* in_sizes, int n_in,
                              void* d_out, int out_size)
{
    (void)in_sizes; (void)n_in; (void)out_size;

    const int*   tokens = (const int*)  d_in[0];
    const float* emb    = (const float*)d_in[1];
    const float* Wq     = (const float*)d_in[2];
    const float* bq     = (const float*)d_in[3];
    const float* Wk     = (const float*)d_in[4];
    const float* bk     = (const float*)d_in[5];
    const float* Wv     = (const float*)d_in[6];
    const float* bv     = (const float*)d_in[7];
    const float* Wo     = (const float*)d_in[8];
    const float* bo     = (const float*)d_in[9];
    const float* W1     = (const float*)d_in[10];
    const float* b1     = (const float*)d_in[11];
    const float* W2     = (const float*)d_in[12];
    const float* b2     = (const float*)d_in[13];
    const float* ln_g   = (const float*)d_in[14];
    const float* ln_b   = (const float*)d_in[15];

    float *x, *q, *k, *v, *attn, *tmp, *h1;
    cudaGetSymbolAddress((void**)&x,    g_x);
    cudaGetSymbolAddress((void**)&q,    g_q);
    cudaGetSymbolAddress((void**)&k,    g_k);
    cudaGetSymbolAddress((void**)&v,    g_v);
    cudaGetSymbolAddress((void**)&attn, g_attn);
    cudaGetSymbolAddress((void**)&tmp,  g_tmp);
    cudaGetSymbolAddress((void**)&h1,   g_h1);

    static bool attr_set = false;
    if (!attr_set) {
        cudaFuncSetAttribute(attn_mma_kernel,
                             cudaFuncAttributeMaxDynamicSharedMemorySize,
                             ATT_SMEM_BYTES);
        attr_set = true;
    }

    embed_kernel<<<(MTOK*DMODEL)/256, 256>>>(tokens, emb, x);

    dim3 gQKV (DMODEL/64, MTOK/128, 3);  // fused q,k,v
    dim3 gProj(DMODEL/64, MTOK/128, 1);
    dim3 gFF1 (FFDIM/64,  MTOK/128, 1);
    dim3 gAttn(SEQ/64, BATCH*NHEADS);

    for (int l = 0; l < NLAYER; l++) {
        const float* wq = Wq + (size_t)l*DMODEL*DMODEL;
        const float* wk = Wk + (size_t)l*DMODEL*DMODEL;
        const float* wv = Wv + (size_t)l*DMODEL*DMODEL;
        const float* wo = Wo + (size_t)l*DMODEL*DMODEL;
        const float* w1 = W1 + (size_t)l*DMODEL*FFDIM;
        const float* w2 = W2 + (size_t)l*FFDIM*DMODEL;

        GemmSet sq = { wq, bq + l*DMODEL, q };
        GemmSet sk = { wk, bk + l*DMODEL, k };
        GemmSet sv = { wv, bv + l*DMODEL, v };
        gemm_tf32_kernel<<<gQKV, 128>>>(x, sq, sk, sv, MTOK, DMODEL, DMODEL, 0);

        attn_mma_kernel<<<gAttn, 128, ATT_SMEM_BYTES>>>(q, k, v, attn);

        GemmSet so = { wo, bo + l*DMODEL, tmp };
        gemm_tf32_kernel<<<gProj, 128>>>(attn, so, so, so, MTOK, DMODEL, DMODEL, 0);
        resln_kernel<<<MTOK/8, 256>>>(x, tmp, ln_g + l*DMODEL, ln_b + l*DMODEL, x);

        GemmSet s1 = { w1, b1 + l*FFDIM, h1 };
        gemm_tf32_kernel<<<gFF1, 128>>>(x, s1, s1, s1, MTOK, FFDIM, DMODEL, 1);
        GemmSet s2 = { w2, b2 + l*DMODEL, tmp };
        gemm_tf32_kernel<<<gProj, 128>>>(h1, s2, s2, s2, MTOK, DMODEL, FFDIM, 0);

        float* dst = (l == NLAYER-1) ? (float*)d_out : x;
        resln_kernel<<<MTOK/8, 256>>>(x, tmp, ln_g + l*DMODEL, ln_b + l*DMODEL, dst);
    }
}